// round 12
// baseline (speedup 1.0000x reference)
#include <cuda_runtime.h>
#include <math.h>

#define PI_F 3.14159265358979323846

// Direct bilinear gather, warp-tiled 8x4 for L1 locality (proven in R11).
// New this round: rotation params computed once per warp (lane 0 + shfl
// broadcast) instead of per thread, and all indexing in 32-bit.

constexpr int BLOCK = 256;

__global__ void __launch_bounds__(BLOCK) affine_warp_tile_kernel(
    const float* __restrict__ x,      // [B, 3, H, W]
    const float* __restrict__ angles, // [B]
    float* __restrict__ out,          // [B, 3, S, S]
    int H, int W, int S, int ntx)
{
    const int b = blockIdx.y;
    const int t = blockIdx.x;
    const int tx = t % ntx;           // 32-wide regions across
    const int ty = t / ntx;           // 8-tall regions down

    const int tid  = threadIdx.x;
    const int lane = tid & 31;
    const int w    = tid >> 5;        // warp 0..7

    // Rotation params: lane 0 computes, broadcast to the warp.
    float c, s;
    {
        float cv = 0.0f, sv = 0.0f;
        if (lane == 0) {
            const float rad = angles[b] * (float)(PI_F / 180.0);
            float sn, cs;
            sincosf(rad, &sn, &cs);
            const float scl = fabsf(cs) + fabsf(sn);
            cv = cs / scl;
            sv = sn / scl;
        }
        c = __shfl_sync(0xFFFFFFFFu, cv, 0);
        s = __shfl_sync(0xFFFFFFFFu, sv, 0);
    }

    // warp position inside the 32x8 block region: 4 across x, 2 down y
    const int ox = tx * 32 + (w & 3) * 8 + (lane & 7);
    const int oy = ty * 8  + (w >> 2) * 4 + (lane >> 3);
    if (ox >= S || oy >= S) return;

    const float step = 2.0f / (float)S;
    const float xs = ((float)ox + 0.5f) * step - 1.0f;
    const float ys = ((float)oy + 0.5f) * step - 1.0f;

    const float gx = c * xs - s * ys;
    const float gy = s * xs + c * ys;

    const float ix = ((gx + 1.0f) * (float)W - 1.0f) * 0.5f;
    const float iy = ((gy + 1.0f) * (float)H - 1.0f) * 0.5f;

    const float x0f = floorf(ix);
    const float y0f = floorf(iy);
    const int x0 = (int)x0f;
    const int y0 = (int)y0f;
    const int x1 = x0 + 1;
    const int y1 = y0 + 1;

    const float wx1 = ix - x0f;
    const float wx0 = 1.0f - wx1;
    const float wy1 = iy - y0f;
    const float wy0 = 1.0f - wy1;

    const bool inx0 = (x0 >= 0) & (x0 < W);
    const bool inx1 = (x1 >= 0) & (x1 < W);
    const bool iny0 = (y0 >= 0) & (y0 < H);
    const bool iny1 = (y1 >= 0) & (y1 < H);

    // Fold zero-padding masks into the bilinear weights (branchless).
    const float w00 = (inx0 & iny0) ? (wy0 * wx0) : 0.0f;
    const float w01 = (inx1 & iny0) ? (wy0 * wx1) : 0.0f;
    const float w10 = (inx0 & iny1) ? (wy1 * wx0) : 0.0f;
    const float w11 = (inx1 & iny1) ? (wy1 * wx1) : 0.0f;

    const int x0c = min(max(x0, 0), W - 1);
    const int x1c = min(max(x1, 0), W - 1);
    const int y0c = min(max(y0, 0), H - 1);
    const int y1c = min(max(y1, 0), H - 1);

    // 32-bit indexing: total elements 64*3*512*512 = 50.3M < 2^31.
    const int HW  = H * W;            // 262144
    const int SSo = S * S;            // 50176
    const int i00 = y0c * W + x0c;
    const int i01 = y0c * W + x1c;
    const int i10 = y1c * W + x0c;
    const int i11 = y1c * W + x1c;

    const float* img = x + b * 3 * HW;
    float* obase = out + b * 3 * SSo + oy * S + ox;

    #pragma unroll 3
    for (int ch = 0; ch < 3; ++ch) {
        const float* p = img + ch * HW;
        float v = w00 * __ldg(p + i00)
                + w01 * __ldg(p + i01)
                + w10 * __ldg(p + i10)
                + w11 * __ldg(p + i11);
        obase[ch * SSo] = v;
    }
}

extern "C" void kernel_launch(void* const* d_in, const int* in_sizes, int n_in,
                              void* d_out, int out_size)
{
    const float* x = (const float*)d_in[0];
    const float* angles = (const float*)d_in[1];
    float* out = (float*)d_out;

    const int B = in_sizes[1];
    const int C = 3;
    const long long hw = (long long)in_sizes[0] / ((long long)B * C);
    const int H = (int)(sqrt((double)hw) + 0.5);
    const int W = H;
    const long long ss = (long long)out_size / ((long long)B * C);
    const int S = (int)(sqrt((double)ss) + 0.5);

    const int ntx = (S + 31) / 32;    // 32-wide block regions
    const int nty = (S + 7) / 8;      // 8-tall block regions

    dim3 grid(ntx * nty, B, 1);
    affine_warp_tile_kernel<<<grid, BLOCK>>>(x, angles, out, H, W, S, ntx);
}